// round 16
// baseline (speedup 1.0000x reference)
#include <cuda_runtime.h>
#include <cuda_bf16.h>
#include <cuda_fp16.h>
#include <math.h>
#include <stdint.h>

// ---------------- problem constants ----------------
#define D_MODEL 1024
#define HIDDEN  1024
#define NHEADS  16
#define DHEAD   64
#define NTOK    8192          // B*S
#define SEQ     2048
#define RANK    256
#define TOPK    4
#define NBIG    5120          // q(1024) k v gate(3072..4095) ogate(4096..5119); decay separate
#define COL_OGATE 4096
#define NCHUNK  32
#define CHUNKSZ 64

// ---------------- scratch (device globals; allocation-free rule) ----------------
__device__ __nv_bfloat16 g_xhi [NTOK * D_MODEL];
__device__ __nv_bfloat16 g_xlo [NTOK * D_MODEL];
__device__ __half        g_x16 [NTOK * D_MODEL];
__device__ __nv_bfloat16 g_WThi[4096 * D_MODEL];     // q/k/v/gate W_eff^T rows (weff output)
__device__ __nv_bfloat16 g_WTlo[4096 * D_MODEL];
__device__ __half        g_W16 [2048 * D_MODEL];     // rows: 0..1023 gate (n-3072), 1024..2047 ogate
__device__ __nv_bfloat16 g_VThi[4 * HIDDEN * 1024];
__device__ __nv_bfloat16 g_VTlo[4 * HIDDEN * 1024];
__device__ __nv_bfloat16 g_Uchi[4 * D_MODEL * 1024];
__device__ __nv_bfloat16 g_Uclo[4 * D_MODEL * 1024];
__device__ __nv_bfloat16 g_ophi[D_MODEL * HIDDEN];
__device__ __nv_bfloat16 g_oplo[D_MODEL * HIDDEN];
__device__ __nv_bfloat16 g_yhi [NTOK * HIDDEN];
__device__ __nv_bfloat16 g_ylo [NTOK * HIDDEN];
__device__ float g_pre [NTOK * NBIG];
__device__ float g_ldz [NTOK * NHEADS];              // fp32 decay logits
__device__ float g_kv  [NTOK * HIDDEN];
__device__ float g_ld  [NTOK * NHEADS];
__device__ float g_out [NTOK * HIDDEN];
__device__ float g_Y   [4 * NHEADS * NCHUNK * DHEAD];
__device__ float g_Sin [4 * NHEADS * NCHUNK * DHEAD];
__device__ float g_Adec[4 * NHEADS * NCHUNK];
__device__ float g_vals[4][TOPK];
__device__ int   g_idx [4][TOPK];

// ---------------- helpers ----------------
__device__ __forceinline__ uint32_t smem_u32(const void* p) {
    uint32_t a;
    asm("{ .reg .u64 t; cvta.to.shared.u64 t, %1; cvt.u32.u64 %0, t; }" : "=r"(a) : "l"(p));
    return a;
}
__device__ __forceinline__ uint32_t sw128(uint32_t off) { return off ^ ((off >> 3) & 0x70); }

__device__ __forceinline__ void ldsm4(uint32_t* r, uint32_t addr) {
    asm volatile("ldmatrix.sync.aligned.m8n8.x4.shared.b16 {%0,%1,%2,%3}, [%4];"
        : "=r"(r[0]), "=r"(r[1]), "=r"(r[2]), "=r"(r[3]) : "r"(addr));
}
__device__ __forceinline__ void mma_bf16(float* c, const uint32_t* a, const uint32_t* b) {
    asm volatile("mma.sync.aligned.m16n8k16.row.col.f32.bf16.bf16.f32 "
        "{%0,%1,%2,%3}, {%4,%5,%6,%7}, {%8,%9}, {%0,%1,%2,%3};"
        : "+f"(c[0]), "+f"(c[1]), "+f"(c[2]), "+f"(c[3])
        : "r"(a[0]), "r"(a[1]), "r"(a[2]), "r"(a[3]), "r"(b[0]), "r"(b[1]));
}
__device__ __forceinline__ void mma_f16(float* c, const uint32_t* a, const uint32_t* b) {
    asm volatile("mma.sync.aligned.m16n8k16.row.col.f32.f16.f16.f32 "
        "{%0,%1,%2,%3}, {%4,%5,%6,%7}, {%8,%9}, {%0,%1,%2,%3};"
        : "+f"(c[0]), "+f"(c[1]), "+f"(c[2]), "+f"(c[3])
        : "r"(a[0]), "r"(a[1]), "r"(a[2]), "r"(a[3]), "r"(b[0]), "r"(b[1]));
}
__device__ __forceinline__ void cp16(uint32_t dst, const void* src) {
    asm volatile("cp.async.cg.shared.global [%0], [%1], 16;" :: "r"(dst), "l"(src) : "memory");
}

#define NTHREADS 256

// ================= bf16 3-term engine (R13, unchanged) =================
#define STAGE_BYTES 98304
#define SMEM_GEMM   (2 * STAGE_BYTES)

template <int EPI, int KV>
__device__ void gemm_tc_body(
    const __nv_bfloat16* __restrict__ Ahi, const __nv_bfloat16* __restrict__ Alo,
    const __nv_bfloat16* __restrict__ Bhi, const __nv_bfloat16* __restrict__ Blo,
    int mBase, int nBase, int mOut,
    float* __restrict__ C, __nv_bfloat16* __restrict__ Chi, __nv_bfloat16* __restrict__ Clo,
    int ldc)
{
    extern __shared__ char smem[];
    const uint32_t sbase = smem_u32(smem);
    const int tid  = threadIdx.x;
    const int wid  = tid >> 5, lane = tid & 31;
    const int wm   = wid & 3,  wn   = wid >> 2;

    float acc[4][8][4];
#pragma unroll
    for (int i = 0; i < 4; i++)
#pragma unroll
        for (int j = 0; j < 8; j++)
#pragma unroll
            for (int q = 0; q < 4; q++) acc[i][j][q] = 0.f;

    const int r0 = tid >> 3, c16v = tid & 7;
    const __nv_bfloat16* pAhi = Ahi + (size_t)(mBase + r0) * KV + c16v * 8;
    const __nv_bfloat16* pAlo = Alo + (size_t)(mBase + r0) * KV + c16v * 8;
    const __nv_bfloat16* pBhi = Bhi + (size_t)(nBase + r0) * KV + c16v * 8;
    const __nv_bfloat16* pBlo = Blo + (size_t)(nBase + r0) * KV + c16v * 8;
    const uint32_t swz0 = sw128((uint32_t)r0 * 128u + (uint32_t)c16v * 16u);

    auto issue = [&](uint32_t stg) {
        const uint32_t d0 = stg + swz0;
#pragma unroll
        for (int j = 0; j < 8; j++) cp16(d0 +           j * 4096u, pAhi + (size_t)j * 32 * KV);
#pragma unroll
        for (int j = 0; j < 8; j++) cp16(d0 + 32768u +  j * 4096u, pAlo + (size_t)j * 32 * KV);
#pragma unroll
        for (int j = 0; j < 4; j++) cp16(d0 + 65536u +  j * 4096u, pBhi + (size_t)j * 32 * KV);
#pragma unroll
        for (int j = 0; j < 4; j++) cp16(d0 + 81920u +  j * 4096u, pBlo + (size_t)j * 32 * KV);
        asm volatile("cp.async.commit_group;" ::: "memory");
        pAhi += 64; pAlo += 64; pBhi += 64; pBlo += 64;
    };

    const int g = lane >> 3, r = lane & 7;
    const uint32_t a_row  = (uint32_t)(wm * 64 + (g & 1) * 8 + r);
    const uint32_t a_colb = (uint32_t)((g >> 1) * 16);
    const uint32_t b_row  = (uint32_t)(wn * 64 + (g >> 1) * 8 + r);
    const uint32_t b_colb = (uint32_t)((g & 1) * 16);

    constexpr int NC = KV >> 6;
    issue(sbase);

    for (int c = 0; c < NC; c++) {
        const int buf = c & 1;
        if (c + 1 < NC) {
            issue(sbase + (uint32_t)(buf ^ 1) * STAGE_BYTES);
            asm volatile("cp.async.wait_group 1;" ::: "memory");
        } else {
            asm volatile("cp.async.wait_group 0;" ::: "memory");
        }
        __syncthreads();

        const uint32_t stage = sbase + (uint32_t)buf * STAGE_BYTES;
        const uint32_t Ah = stage, Al = stage + 32768u, Bh = stage + 65536u, Bl = stage + 81920u;
#pragma unroll
        for (int k16 = 0; k16 < 4; k16++) {
            uint32_t ahi[4][4], alo[4][4];
#pragma unroll
            for (int i = 0; i < 4; i++) {
                uint32_t off = sw128((a_row + (uint32_t)i * 16u) * 128u
                                     + (uint32_t)k16 * 32u + a_colb);
                ldsm4(ahi[i], Ah + off);
                ldsm4(alo[i], Al + off);
            }
            uint32_t bb[2][2][4];
            {
                uint32_t off = sw128(b_row * 128u + (uint32_t)k16 * 32u + b_colb);
                ldsm4(bb[0][0], Bh + off);
                ldsm4(bb[0][1], Bl + off);
            }
#pragma unroll
            for (int j2 = 0; j2 < 4; j2++) {
                const int cur = j2 & 1, nxt = cur ^ 1;
                if (j2 < 3) {
                    uint32_t off = sw128((b_row + (uint32_t)(j2 + 1) * 16u) * 128u
                                         + (uint32_t)k16 * 32u + b_colb);
                    ldsm4(bb[nxt][0], Bh + off);
                    ldsm4(bb[nxt][1], Bl + off);
                }
                const uint32_t* bh0 = bb[cur][0];
                const uint32_t* bh1 = bb[cur][0] + 2;
                const uint32_t* bl0 = bb[cur][1];
                const uint32_t* bl1 = bb[cur][1] + 2;
#pragma unroll
                for (int i = 0; i < 4; i++) {
                    mma_bf16(acc[i][2 * j2],     ahi[i], bh0);
                    mma_bf16(acc[i][2 * j2],     ahi[i], bl0);
                    mma_bf16(acc[i][2 * j2],     alo[i], bh0);
                    mma_bf16(acc[i][2 * j2 + 1], ahi[i], bh1);
                    mma_bf16(acc[i][2 * j2 + 1], ahi[i], bl1);
                    mma_bf16(acc[i][2 * j2 + 1], alo[i], bh1);
                }
            }
        }
        __syncthreads();
    }

    const int rr = lane >> 2, cc = (lane & 3) * 2;
#pragma unroll
    for (int i = 0; i < 4; i++) {
        const int row = mOut + wm * 64 + i * 16 + rr;
#pragma unroll
        for (int j = 0; j < 8; j++) {
            const int col = nBase + wn * 64 + j * 8 + cc;
            if (EPI == 0) {
                *(float2*)(C + (size_t)row * ldc + col)       = make_float2(acc[i][j][0], acc[i][j][1]);
                *(float2*)(C + (size_t)(row + 8) * ldc + col) = make_float2(acc[i][j][2], acc[i][j][3]);
            } else {
#pragma unroll
                for (int hrow = 0; hrow < 2; hrow++) {
                    float v0 = acc[i][j][hrow * 2], v1 = acc[i][j][hrow * 2 + 1];
                    __nv_bfloat16 h0 = __float2bfloat16_rn(v0), h1 = __float2bfloat16_rn(v1);
                    float l0 = v0 - __bfloat162float(h0), l1 = v1 - __bfloat162float(h1);
                    __nv_bfloat162 hh = __halves2bfloat162(h0, h1);
                    __nv_bfloat162 ll = __halves2bfloat162(__float2bfloat16_rn(l0), __float2bfloat16_rn(l1));
                    const size_t off = (size_t)(row + hrow * 8) * ldc + col;
                    *(uint32_t*)(Chi + off) = *(uint32_t*)&hh;
                    *(uint32_t*)(Clo + off) = *(uint32_t*)&ll;
                }
            }
        }
    }
}

// ================= fp16 single-term engine (gates path) =================
// C[256,128] fp32 = A(f16)[M,K] * B(f16)[N,K]^T. Stage 48KB: [A 32KB][B 16KB].
#define STAGE_H 49152
#define SMEM_H  (2 * STAGE_H)

template <int KV>
__device__ void gemm_h1_body(
    const __half* __restrict__ A, const __half* __restrict__ B,
    int mBase, int nBaseB, int nColOut, float* __restrict__ C, int ldc)
{
    extern __shared__ char smem[];
    const uint32_t sbase = smem_u32(smem);
    const int tid  = threadIdx.x;
    const int wid  = tid >> 5, lane = tid & 31;
    const int wm   = wid & 3,  wn   = wid >> 2;

    float acc[4][8][4];
#pragma unroll
    for (int i = 0; i < 4; i++)
#pragma unroll
        for (int j = 0; j < 8; j++)
#pragma unroll
            for (int q = 0; q < 4; q++) acc[i][j][q] = 0.f;

    const int r0 = tid >> 3, c16v = tid & 7;
    const __half* pA = A + (size_t)(mBase + r0) * KV + c16v * 8;
    const __half* pB = B + (size_t)(nBaseB + r0) * KV + c16v * 8;
    const uint32_t swz0 = sw128((uint32_t)r0 * 128u + (uint32_t)c16v * 16u);

    auto issue = [&](uint32_t stg) {
        const uint32_t d0 = stg + swz0;
#pragma unroll
        for (int j = 0; j < 8; j++) cp16(d0 +          j * 4096u, pA + (size_t)j * 32 * KV);
#pragma unroll
        for (int j = 0; j < 4; j++) cp16(d0 + 32768u + j * 4096u, pB + (size_t)j * 32 * KV);
        asm volatile("cp.async.commit_group;" ::: "memory");
        pA += 64; pB += 64;
    };

    const int g = lane >> 3, r = lane & 7;
    const uint32_t a_row  = (uint32_t)(wm * 64 + (g & 1) * 8 + r);
    const uint32_t a_colb = (uint32_t)((g >> 1) * 16);
    const uint32_t b_row  = (uint32_t)(wn * 64 + (g >> 1) * 8 + r);
    const uint32_t b_colb = (uint32_t)((g & 1) * 16);

    constexpr int NC = KV >> 6;
    issue(sbase);

    for (int c = 0; c < NC; c++) {
        const int buf = c & 1;
        if (c + 1 < NC) {
            issue(sbase + (uint32_t)(buf ^ 1) * STAGE_H);
            asm volatile("cp.async.wait_group 1;" ::: "memory");
        } else {
            asm volatile("cp.async.wait_group 0;" ::: "memory");
        }
        __syncthreads();

        const uint32_t stage = sbase + (uint32_t)buf * STAGE_H;
        const uint32_t Ah = stage, Bh = stage + 32768u;
#pragma unroll
        for (int k16 = 0; k16 < 4; k16++) {
            uint32_t af[4][4];
#pragma unroll
            for (int i = 0; i < 4; i++) {
                uint32_t off = sw128((a_row + (uint32_t)i * 16u) * 128u
                                     + (uint32_t)k16 * 32u + a_colb);
                ldsm4(af[i], Ah + off);
            }
            uint32_t bf[2][4];
            {
                uint32_t off = sw128(b_row * 128u + (uint32_t)k16 * 32u + b_colb);
                ldsm4(bf[0], Bh + off);
            }
#pragma unroll
            for (int j2 = 0; j2 < 4; j2++) {
                const int cur = j2 & 1, nxt = cur ^ 1;
                if (j2 < 3) {
                    uint32_t off = sw128((b_row + (uint32_t)(j2 + 1) * 16u) * 128u
                                         + (uint32_t)k16 * 32u + b_colb);
                    ldsm4(bf[nxt], Bh + off);
                }
#pragma unroll
                for (int i = 0; i < 4; i++) {
                    mma_f16(acc[i][2 * j2],     af[i], bf[cur]);
                    mma_f16(acc[i][2 * j2 + 1], af[i], bf[cur] + 2);
                }
            }
        }
        __syncthreads();
    }

    const int rr = lane >> 2, cc = (lane & 3) * 2;
#pragma unroll
    for (int i = 0; i < 4; i++) {
        const int row = mBase + wm * 64 + i * 16 + rr;
#pragma unroll
        for (int j = 0; j < 8; j++) {
            const int col = nColOut + wn * 64 + j * 8 + cc;
            *(float2*)(C + (size_t)row * ldc + col)       = make_float2(acc[i][j][0], acc[i][j][1]);
            *(float2*)(C + (size_t)(row + 8) * ldc + col) = make_float2(acc[i][j][2], acc[i][j][3]);
        }
    }
}

// ---------------- GEMM wrapper kernels ----------------
__global__ void __launch_bounds__(NTHREADS, 1) k_pre_gemm()        // q/k/v cols 0..3071, bf16 pair
{
    const int mBase = blockIdx.y * 256, nBase = blockIdx.x * 128;
    gemm_tc_body<0, 1024>(g_xhi, g_xlo, g_WThi, g_WTlo, mBase, nBase, mBase,
                          g_pre, nullptr, nullptr, NBIG);
}

__global__ void __launch_bounds__(NTHREADS, 1) k_pre_gemm_h()      // gate+ogate cols 3072..5119, fp16
{
    const int mBase = blockIdx.y * 256, nB = blockIdx.x * 128;     // nB in [0,2048)
    gemm_h1_body<1024>(g_x16, g_W16, mBase, nB, 3072 + nB, g_pre, NBIG);
}

__global__ void __launch_bounds__(NTHREADS, 1) k_weff_gemm()
{
    const int p = blockIdx.z;
    const int mBase = blockIdx.y * 256, nBase = blockIdx.x * 128;
    const size_t off = (size_t)p * 1024 * 1024;
    gemm_tc_body<1, 1024>(g_VThi + off, g_VTlo + off, g_Uchi + off, g_Uclo + off,
                          mBase, nBase, p * 1024 + mBase,
                          nullptr, g_WThi, g_WTlo, D_MODEL);
}

__global__ void __launch_bounds__(NTHREADS, 1) k_final_gemm(float* __restrict__ out)
{
    const int mBase = blockIdx.y * 256, nBase = blockIdx.x * 128;
    gemm_tc_body<0, 1024>(g_yhi, g_ylo, g_ophi, g_oplo, mBase, nBase, mBase,
                          out, nullptr, nullptr, D_MODEL);
}

// ---------------- prep kernels ----------------
__global__ void topk_setup(const float* __restrict__ ql, const float* __restrict__ kl,
                           const float* __restrict__ vl, const float* __restrict__ gl)
{
    if (threadIdx.x != 0) return;
    const float* Ls[4] = {ql, kl, vl, gl};
    for (int p = 0; p < 4; p++) {
        float l[16];
        float m = -1e30f;
        for (int i = 0; i < 16; i++) { l[i] = Ls[p][i]; m = fmaxf(m, l[i]); }
        bool used[16] = {false};
        float s = 0.f;
        for (int k = 0; k < TOPK; k++) {
            int best = -1; float bvv = -1e30f;
            for (int i = 0; i < 16; i++)
                if (!used[i] && l[i] > bvv) { bvv = l[i]; best = i; }
            used[best] = true;
            g_idx[p][k] = best;
            float e = expf(l[best] - m);
            g_vals[p][k] = e;
            s += e;
        }
        for (int k = 0; k < TOPK; k++) g_vals[p][k] /= s;
    }
}

__global__ void conv_pair4(const float* __restrict__ src,
                           __nv_bfloat16* __restrict__ hi, __nv_bfloat16* __restrict__ lo, int n4)
{
    int i = blockIdx.x * 256 + threadIdx.x;
    if (i >= n4) return;
    float4 v = ((const float4*)src)[i];
    __nv_bfloat16 h0 = __float2bfloat16_rn(v.x), h1 = __float2bfloat16_rn(v.y);
    __nv_bfloat16 h2 = __float2bfloat16_rn(v.z), h3 = __float2bfloat16_rn(v.w);
    __nv_bfloat162 hA = __halves2bfloat162(h0, h1), hB = __halves2bfloat162(h2, h3);
    __nv_bfloat162 lA = __halves2bfloat162(__float2bfloat16_rn(v.x - __bfloat162float(h0)),
                                           __float2bfloat16_rn(v.y - __bfloat162float(h1)));
    __nv_bfloat162 lB = __halves2bfloat162(__float2bfloat16_rn(v.z - __bfloat162float(h2)),
                                           __float2bfloat16_rn(v.w - __bfloat162float(h3)));
    ((uint2*)hi)[i] = make_uint2(*(uint32_t*)&hA, *(uint32_t*)&hB);
    ((uint2*)lo)[i] = make_uint2(*(uint32_t*)&lA, *(uint32_t*)&lB);
}

__global__ void conv_h4(const float* __restrict__ src, __half* __restrict__ dst, int n4)
{
    int i = blockIdx.x * 256 + threadIdx.x;
    if (i >= n4) return;
    float4 v = ((const float4*)src)[i];
    __half2 a = __floats2half2_rn(v.x, v.y);
    __half2 b = __floats2half2_rn(v.z, v.w);
    ((uint2*)dst)[i] = make_uint2(*(uint32_t*)&a, *(uint32_t*)&b);
}

// Uc(p)[d, ks*256+r] = U_p[prim(ks)][d, r]
__global__ void build_Uc(const float* __restrict__ qU, const float* __restrict__ kU,
                         const float* __restrict__ vU)
{
    const int p = blockIdx.y;
    const float* U = (p == 0) ? qU : (p == 1) ? kU : vU;
    int i = blockIdx.x * 256 + threadIdx.x;
    int d = i >> 10, kk = i & 1023, ks = kk >> 8, rr = kk & 255;
    int prim = g_idx[p][ks];
    float v = U[(size_t)prim * (D_MODEL * RANK) + (size_t)d * RANK + rr];
    __nv_bfloat16 h = __float2bfloat16_rn(v);
    size_t off = (size_t)p * 1048576 + i;
    g_Uchi[off] = h;
    g_Uclo[off] = __float2bfloat16_rn(v - __bfloat162float(h));
}

// VT(p)[o, ks*256+r] = vals[p][ks] * V_p[prim(ks)][r, o]
__global__ void build_VT(const float* __restrict__ qV, const float* __restrict__ kV,
                         const float* __restrict__ vV)
{
    __shared__ float tile[32][33];
    const int z = blockIdx.z;
    const int p = z >> 2, ks = z & 3;
    const float* V = (p == 0) ? qV : (p == 1) ? kV : vV;
    const int prim = g_idx[p][ks];
    const float w = g_vals[p][ks];
    const float* Vp = V + (size_t)prim * (RANK * HIDDEN);
    const int r0 = blockIdx.x * 32, o0 = blockIdx.y * 32;
#pragma unroll
    for (int j = 0; j < 32; j += 8)
        tile[threadIdx.y + j][threadIdx.x] = Vp[(size_t)(r0 + threadIdx.y + j) * HIDDEN + o0 + threadIdx.x];
    __syncthreads();
#pragma unroll
    for (int j = 0; j < 32; j += 8) {
        float v = w * tile[threadIdx.x][threadIdx.y + j];
        size_t off = (size_t)p * 1048576 + (size_t)(o0 + threadIdx.y + j) * 1024 + ks * 256 + r0 + threadIdx.x;
        __nv_bfloat16 h = __float2bfloat16_rn(v);
        g_VThi[off] = h;
        g_VTlo[off] = __float2bfloat16_rn(v - __bfloat162float(h));
    }
}

// gate rows: g_W16[0..1023] = fp16(WThi+WTlo rows 3072..4095)
__global__ void repack_gate(void)
{
    int i = blockIdx.x * 256 + threadIdx.x;      // over 1024*1024
    size_t src = (size_t)(3072) * 1024 + i;
    float v = __bfloat162float(g_WThi[src]) + __bfloat162float(g_WTlo[src]);
    g_W16[i] = __float2half_rn(v);
}

// ogate rows: g_W16[1024..2047] = fp16(out_gate_w)
__global__ void pack_ogate(const float* __restrict__ ogw)
{
    int i = blockIdx.x * 256 + threadIdx.x;      // over 1024*1024
    g_W16[1048576 + i] = __float2half_rn(ogw[i]);
}

// fp32 decay logits: z[t][h] = x[t] . decay_w[h]
__global__ void decay_z(const float* __restrict__ x, const float* __restrict__ dw)
{
    int idx = blockIdx.x * 256 + threadIdx.x;    // over NTOK*16
    int row = idx >> 4, h = idx & 15;
    const float4* xr = (const float4*)(x + (size_t)row * 1024);
    const float4* wr = (const float4*)(dw + (size_t)h * 1024);
    float acc = 0.f;
    for (int k = 0; k < 256; k++) {
        float4 a = xr[k], b = wr[k];
        acc += a.x * b.x + a.y * b.y + a.z * b.z + a.w * b.w;
    }
    g_ldz[idx] = acc;
}

// ---------------- pointwise: kv = sigmoid(gate)*k*v ; log_decay = -softplus(z + b) ----------------
__global__ void pointwise(const float* __restrict__ decay_b)
{
    const int row = blockIdx.y;
    const int col = blockIdx.x * 256 + threadIdx.x;
    const size_t base = (size_t)row * NBIG;
    float kk = g_pre[base + 1024 + col];
    float vv = g_pre[base + 2048 + col];
    float gt = g_pre[base + 3072 + col];
    g_kv[(size_t)row * HIDDEN + col] = kk * vv / (1.f + expf(-gt));
    if (blockIdx.x == 0 && threadIdx.x < NHEADS) {
        float z = g_ldz[row * NHEADS + threadIdx.x] + decay_b[threadIdx.x];
        float sp = fmaxf(z, 0.f) + log1pf(expf(-fabsf(z)));
        g_ld[row * NHEADS + threadIdx.x] = -sp;
    }
}

// ---------------- chunked scan ----------------
__global__ void scan_pass1()
{
    const int b = blockIdx.z, h = blockIdx.y, c = blockIdx.x, d = threadIdx.x;
    const int row0 = b * SEQ + c * CHUNKSZ;
    float s = 0.f, cum = 0.f;
    for (int t = 0; t < CHUNKSZ; t++) {
        const int row = row0 + t;
        float ld = g_ld[row * NHEADS + h];
        cum += ld;
        s = s * expf(ld) + g_kv[(size_t)row * HIDDEN + h * DHEAD + d];
    }
    const int ci = (b * NHEADS + h) * NCHUNK + c;
    g_Y[ci * DHEAD + d] = s;
    if (d == 0) g_Adec[ci] = expf(cum);
}

__global__ void scan_pass2()
{
    const int h = blockIdx.x, b = blockIdx.y, d = threadIdx.x;
    const int base = (b * NHEADS + h) * NCHUNK;
    float s = 0.f;
    for (int c = 0; c < NCHUNK; c++) {
        g_Sin[(base + c) * DHEAD + d] = s;
        s = g_Adec[base + c] * s + g_Y[(base + c) * DHEAD + d];
    }
}

__global__ void scan_pass3()
{
    const int b = blockIdx.z, h = blockIdx.y, c = blockIdx.x, d = threadIdx.x;
    const int ci = (b * NHEADS + h) * NCHUNK + c;
    const int row0 = b * SEQ + c * CHUNKSZ;
    float s = g_Sin[ci * DHEAD + d];
    for (int t = 0; t < CHUNKSZ; t++) {
        const int row = row0 + t;
        float ld = g_ld[row * NHEADS + h];
        s = s * expf(ld) + g_kv[(size_t)row * HIDDEN + h * DHEAD + d];
        float q = g_pre[(size_t)row * NBIG + h * DHEAD + d];
        g_out[(size_t)row * HIDDEN + h * DHEAD + d] = q * s;
    }
}

// ---------------- RMS-norm + output gate -> bf16 pair ----------------
__global__ void rms_gate(const float* __restrict__ rms_w)
{
    const int row = blockIdx.x;
    const int tid = threadIdx.x;
    const float* o = g_out + (size_t)row * HIDDEN;
    float ss = 0.f;
    for (int c = tid; c < HIDDEN; c += 256) { float x = o[c]; ss += x * x; }
#pragma unroll
    for (int w = 16; w; w >>= 1) ss += __shfl_xor_sync(0xffffffffu, ss, w);
    __shared__ float red[8];
    if ((tid & 31) == 0) red[tid >> 5] = ss;
    __syncthreads();
    __shared__ float s_rinv;
    if (tid < 8) {
        float v = red[tid];
#pragma unroll
        for (int w = 4; w; w >>= 1) v += __shfl_xor_sync(0xffu, v, w);
        if (tid == 0) s_rinv = rsqrtf(v * (1.f / 1024.f) + 1.1920929e-07f);
    }
    __syncthreads();
    const float rinv = s_rinv;
    for (int c = tid; c < HIDDEN; c += 256) {
        float g = g_pre[(size_t)row * NBIG + COL_OGATE + c];
        float y = o[c] * rinv * rms_w[c] / (1.f + expf(-g));
        __nv_bfloat16 h = __float2bfloat16_rn(y);
        size_t off = (size_t)row * HIDDEN + c;
        g_yhi[off] = h;
        g_ylo[off] = __float2bfloat16_rn(y - __bfloat162float(h));
    }
}

// ---------------- launch ----------------
extern "C" void kernel_launch(void* const* d_in, const int* in_sizes, int n_in,
                              void* d_out, int out_size)
{
    (void)in_sizes; (void)n_in; (void)out_size;
    const float* x    = (const float*)d_in[0];
    const float* qU   = (const float*)d_in[1];
    const float* qV   = (const float*)d_in[2];
    const float* kU   = (const float*)d_in[3];
    const float* kV   = (const float*)d_in[4];
    const float* vU   = (const float*)d_in[5];
    const float* vV   = (const float*)d_in[6];
    const float* ql   = (const float*)d_in[7];
    const float* kl   = (const float*)d_in[8];
    const float* vl   = (const float*)d_in[9];
    const float* gl   = (const float*)d_in[10];
    const float* dw   = (const float*)d_in[11];
    const float* db   = (const float*)d_in[12];
    const float* ogw  = (const float*)d_in[13];
    const float* opw  = (const float*)d_in[14];
    const float* rmsw = (const float*)d_in[15];
    float* out = (float*)d_out;

    void *p_xhi, *p_xlo, *p_x16, *p_ophi, *p_oplo;
    cudaGetSymbolAddress(&p_xhi,  g_xhi);
    cudaGetSymbolAddress(&p_xlo,  g_xlo);
    cudaGetSymbolAddress(&p_x16,  g_x16);
    cudaGetSymbolAddress(&p_ophi, g_ophi);
    cudaGetSymbolAddress(&p_oplo, g_oplo);

    cudaFuncSetAttribute(k_pre_gemm,   cudaFuncAttributeMaxDynamicSharedMemorySize, SMEM_GEMM);
    cudaFuncSetAttribute(k_pre_gemm_h, cudaFuncAttributeMaxDynamicSharedMemorySize, SMEM_H);
    cudaFuncSetAttribute(k_weff_gemm,  cudaFuncAttributeMaxDynamicSharedMemorySize, SMEM_GEMM);
    cudaFuncSetAttribute(k_final_gemm, cudaFuncAttributeMaxDynamicSharedMemorySize, SMEM_GEMM);

    // launch order keeps k_weff_gemm as launch #3 (profiled)
    topk_setup<<<1, 32>>>(ql, kl, vl, gl);                                   // 0
    build_Uc<<<dim3(4096, 4), 256>>>(qU, kU, vU);                            // 1
    build_VT<<<dim3(8, 32, 16), dim3(32, 8)>>>(qV, kV, vV);                  // 2
    k_weff_gemm<<<dim3(8, 4, 4), NTHREADS, SMEM_GEMM>>>();                   // 3 (profiled)
    conv_pair4<<<(NTOK * D_MODEL / 4 + 255) / 256, 256>>>(x, (__nv_bfloat16*)p_xhi, (__nv_bfloat16*)p_xlo, NTOK * D_MODEL / 4);
    conv_h4<<<(NTOK * D_MODEL / 4 + 255) / 256, 256>>>(x, (__half*)p_x16, NTOK * D_MODEL / 4);
    conv_pair4<<<(D_MODEL * HIDDEN / 4 + 255) / 256, 256>>>(opw, (__nv_bfloat16*)p_ophi, (__nv_bfloat16*)p_oplo, D_MODEL * HIDDEN / 4);
    repack_gate<<<4096, 256>>>();                       // gate W -> fp16 (after weff)
    pack_ogate<<<4096, 256>>>(ogw);                     // ogate W -> fp16
    decay_z<<<NTOK * NHEADS / 256, 256>>>(x, dw);       // fp32 decay logits
    // projection GEMMs: q/k/v (bf16 pair) + gate/ogate (fp16 single)
    k_pre_gemm  <<<dim3(24, NTOK / 256), NTHREADS, SMEM_GEMM>>>();
    k_pre_gemm_h<<<dim3(16, NTOK / 256), NTHREADS, SMEM_H>>>();
    // pointwise kv + log_decay
    pointwise<<<dim3(4, NTOK), 256>>>(db);
    // chunked scan
    scan_pass1<<<dim3(NCHUNK, NHEADS, 4), DHEAD>>>();
    scan_pass2<<<dim3(NHEADS, 4), DHEAD>>>();
    scan_pass3<<<dim3(NCHUNK, NHEADS, 4), DHEAD>>>();
    // RMS norm + output gate (-> bf16 pair)
    rms_gate<<<NTOK, 256>>>(rmsw);
    // final projection
    k_final_gemm<<<dim3(D_MODEL / 128, NTOK / 256), NTHREADS, SMEM_GEMM>>>(out);
}

// round 17
// speedup vs baseline: 1.1769x; 1.1769x over previous
#include <cuda_runtime.h>
#include <cuda_bf16.h>
#include <cuda_fp16.h>
#include <math.h>
#include <stdint.h>

// ---------------- problem constants ----------------
#define D_MODEL 1024
#define HIDDEN  1024
#define NHEADS  16
#define DHEAD   64
#define NTOK    8192          // B*S
#define SEQ     2048
#define RANK    256
#define TOPK    4
// g_pre columns: [q 0..1023][k][v][decay+pad 3072..3199][gate 3200..4223][ogate 4224..5247]
#define NBIG    5248
#define COL_DECAY 3072
#define COL_GATE  3200
#define COL_OGATE 4224
#define NPAIR   3200          // pair-GEMM column count (25 tiles of 128)
#define NCHUNK  32
#define CHUNKSZ 64

// ---------------- scratch (device globals; allocation-free rule) ----------------
__device__ __nv_bfloat16 g_xhi [NTOK * D_MODEL];
__device__ __nv_bfloat16 g_xlo [NTOK * D_MODEL];
__device__ __half        g_x16 [NTOK * D_MODEL];
// pair weights: rows 0..3071 q/k/v W_eff; 3072..3087 decay_w; 3088..3199 zero; 3200..4223 gate W_eff (staging)
__device__ __nv_bfloat16 g_WThi[4224 * D_MODEL];
__device__ __nv_bfloat16 g_WTlo[4224 * D_MODEL];
__device__ __half        g_W16 [2048 * D_MODEL];     // 0..1023 gate, 1024..2047 ogate
__device__ __nv_bfloat16 g_VThi[4 * HIDDEN * 1024];
__device__ __nv_bfloat16 g_VTlo[4 * HIDDEN * 1024];
__device__ __nv_bfloat16 g_Uchi[4 * D_MODEL * 1024];
__device__ __nv_bfloat16 g_Uclo[4 * D_MODEL * 1024];
__device__ __nv_bfloat16 g_ophi[D_MODEL * HIDDEN];
__device__ __nv_bfloat16 g_oplo[D_MODEL * HIDDEN];
__device__ __nv_bfloat16 g_yhi [NTOK * HIDDEN];
__device__ __nv_bfloat16 g_ylo [NTOK * HIDDEN];
__device__ float g_pre [NTOK * NBIG];
__device__ float g_kv  [NTOK * HIDDEN];
__device__ float g_ld  [NTOK * NHEADS];
__device__ float g_out [NTOK * HIDDEN];
__device__ float g_Y   [4 * NHEADS * NCHUNK * DHEAD];
__device__ float g_Sin [4 * NHEADS * NCHUNK * DHEAD];
__device__ float g_Adec[4 * NHEADS * NCHUNK];
__device__ float g_vals[4][TOPK];
__device__ int   g_idx [4][TOPK];

// ---------------- helpers ----------------
__device__ __forceinline__ uint32_t smem_u32(const void* p) {
    uint32_t a;
    asm("{ .reg .u64 t; cvta.to.shared.u64 t, %1; cvt.u32.u64 %0, t; }" : "=r"(a) : "l"(p));
    return a;
}
__device__ __forceinline__ uint32_t sw128(uint32_t off) { return off ^ ((off >> 3) & 0x70); }

__device__ __forceinline__ void ldsm4(uint32_t* r, uint32_t addr) {
    asm volatile("ldmatrix.sync.aligned.m8n8.x4.shared.b16 {%0,%1,%2,%3}, [%4];"
        : "=r"(r[0]), "=r"(r[1]), "=r"(r[2]), "=r"(r[3]) : "r"(addr));
}
__device__ __forceinline__ void mma_bf16(float* c, const uint32_t* a, const uint32_t* b) {
    asm volatile("mma.sync.aligned.m16n8k16.row.col.f32.bf16.bf16.f32 "
        "{%0,%1,%2,%3}, {%4,%5,%6,%7}, {%8,%9}, {%0,%1,%2,%3};"
        : "+f"(c[0]), "+f"(c[1]), "+f"(c[2]), "+f"(c[3])
        : "r"(a[0]), "r"(a[1]), "r"(a[2]), "r"(a[3]), "r"(b[0]), "r"(b[1]));
}
__device__ __forceinline__ void mma_f16(float* c, const uint32_t* a, const uint32_t* b) {
    asm volatile("mma.sync.aligned.m16n8k16.row.col.f32.f16.f16.f32 "
        "{%0,%1,%2,%3}, {%4,%5,%6,%7}, {%8,%9}, {%0,%1,%2,%3};"
        : "+f"(c[0]), "+f"(c[1]), "+f"(c[2]), "+f"(c[3])
        : "r"(a[0]), "r"(a[1]), "r"(a[2]), "r"(a[3]), "r"(b[0]), "r"(b[1]));
}
__device__ __forceinline__ void cp16(uint32_t dst, const void* src) {
    asm volatile("cp.async.cg.shared.global [%0], [%1], 16;" :: "r"(dst), "l"(src) : "memory");
}

#define NTHREADS 256

// ================= bf16 3-term engine (R13, unchanged) =================
#define STAGE_BYTES 98304
#define SMEM_GEMM   (2 * STAGE_BYTES)

template <int EPI, int KV>
__device__ void gemm_tc_body(
    const __nv_bfloat16* __restrict__ Ahi, const __nv_bfloat16* __restrict__ Alo,
    const __nv_bfloat16* __restrict__ Bhi, const __nv_bfloat16* __restrict__ Blo,
    int mBase, int nBase, int mOut, int nColOut,
    float* __restrict__ C, __nv_bfloat16* __restrict__ Chi, __nv_bfloat16* __restrict__ Clo,
    int ldc)
{
    extern __shared__ char smem[];
    const uint32_t sbase = smem_u32(smem);
    const int tid  = threadIdx.x;
    const int wid  = tid >> 5, lane = tid & 31;
    const int wm   = wid & 3,  wn   = wid >> 2;

    float acc[4][8][4];
#pragma unroll
    for (int i = 0; i < 4; i++)
#pragma unroll
        for (int j = 0; j < 8; j++)
#pragma unroll
            for (int q = 0; q < 4; q++) acc[i][j][q] = 0.f;

    const int r0 = tid >> 3, c16v = tid & 7;
    const __nv_bfloat16* pAhi = Ahi + (size_t)(mBase + r0) * KV + c16v * 8;
    const __nv_bfloat16* pAlo = Alo + (size_t)(mBase + r0) * KV + c16v * 8;
    const __nv_bfloat16* pBhi = Bhi + (size_t)(nBase + r0) * KV + c16v * 8;
    const __nv_bfloat16* pBlo = Blo + (size_t)(nBase + r0) * KV + c16v * 8;
    const uint32_t swz0 = sw128((uint32_t)r0 * 128u + (uint32_t)c16v * 16u);

    auto issue = [&](uint32_t stg) {
        const uint32_t d0 = stg + swz0;
#pragma unroll
        for (int j = 0; j < 8; j++) cp16(d0 +           j * 4096u, pAhi + (size_t)j * 32 * KV);
#pragma unroll
        for (int j = 0; j < 8; j++) cp16(d0 + 32768u +  j * 4096u, pAlo + (size_t)j * 32 * KV);
#pragma unroll
        for (int j = 0; j < 4; j++) cp16(d0 + 65536u +  j * 4096u, pBhi + (size_t)j * 32 * KV);
#pragma unroll
        for (int j = 0; j < 4; j++) cp16(d0 + 81920u +  j * 4096u, pBlo + (size_t)j * 32 * KV);
        asm volatile("cp.async.commit_group;" ::: "memory");
        pAhi += 64; pAlo += 64; pBhi += 64; pBlo += 64;
    };

    const int g = lane >> 3, r = lane & 7;
    const uint32_t a_row  = (uint32_t)(wm * 64 + (g & 1) * 8 + r);
    const uint32_t a_colb = (uint32_t)((g >> 1) * 16);
    const uint32_t b_row  = (uint32_t)(wn * 64 + (g >> 1) * 8 + r);
    const uint32_t b_colb = (uint32_t)((g & 1) * 16);

    constexpr int NC = KV >> 6;
    issue(sbase);

    for (int c = 0; c < NC; c++) {
        const int buf = c & 1;
        if (c + 1 < NC) {
            issue(sbase + (uint32_t)(buf ^ 1) * STAGE_BYTES);
            asm volatile("cp.async.wait_group 1;" ::: "memory");
        } else {
            asm volatile("cp.async.wait_group 0;" ::: "memory");
        }
        __syncthreads();

        const uint32_t stage = sbase + (uint32_t)buf * STAGE_BYTES;
        const uint32_t Ah = stage, Al = stage + 32768u, Bh = stage + 65536u, Bl = stage + 81920u;
#pragma unroll
        for (int k16 = 0; k16 < 4; k16++) {
            uint32_t ahi[4][4], alo[4][4];
#pragma unroll
            for (int i = 0; i < 4; i++) {
                uint32_t off = sw128((a_row + (uint32_t)i * 16u) * 128u
                                     + (uint32_t)k16 * 32u + a_colb);
                ldsm4(ahi[i], Ah + off);
                ldsm4(alo[i], Al + off);
            }
            uint32_t bb[2][2][4];
            {
                uint32_t off = sw128(b_row * 128u + (uint32_t)k16 * 32u + b_colb);
                ldsm4(bb[0][0], Bh + off);
                ldsm4(bb[0][1], Bl + off);
            }
#pragma unroll
            for (int j2 = 0; j2 < 4; j2++) {
                const int cur = j2 & 1, nxt = cur ^ 1;
                if (j2 < 3) {
                    uint32_t off = sw128((b_row + (uint32_t)(j2 + 1) * 16u) * 128u
                                         + (uint32_t)k16 * 32u + b_colb);
                    ldsm4(bb[nxt][0], Bh + off);
                    ldsm4(bb[nxt][1], Bl + off);
                }
                const uint32_t* bh0 = bb[cur][0];
                const uint32_t* bh1 = bb[cur][0] + 2;
                const uint32_t* bl0 = bb[cur][1];
                const uint32_t* bl1 = bb[cur][1] + 2;
#pragma unroll
                for (int i = 0; i < 4; i++) {
                    mma_bf16(acc[i][2 * j2],     ahi[i], bh0);
                    mma_bf16(acc[i][2 * j2],     ahi[i], bl0);
                    mma_bf16(acc[i][2 * j2],     alo[i], bh0);
                    mma_bf16(acc[i][2 * j2 + 1], ahi[i], bh1);
                    mma_bf16(acc[i][2 * j2 + 1], ahi[i], bl1);
                    mma_bf16(acc[i][2 * j2 + 1], alo[i], bh1);
                }
            }
        }
        __syncthreads();
    }

    const int rr = lane >> 2, cc = (lane & 3) * 2;
#pragma unroll
    for (int i = 0; i < 4; i++) {
        const int row = mOut + wm * 64 + i * 16 + rr;
#pragma unroll
        for (int j = 0; j < 8; j++) {
            const int col = nColOut + wn * 64 + j * 8 + cc;
            if (EPI == 0) {
                *(float2*)(C + (size_t)row * ldc + col)       = make_float2(acc[i][j][0], acc[i][j][1]);
                *(float2*)(C + (size_t)(row + 8) * ldc + col) = make_float2(acc[i][j][2], acc[i][j][3]);
            } else {
#pragma unroll
                for (int hrow = 0; hrow < 2; hrow++) {
                    float v0 = acc[i][j][hrow * 2], v1 = acc[i][j][hrow * 2 + 1];
                    __nv_bfloat16 h0 = __float2bfloat16_rn(v0), h1 = __float2bfloat16_rn(v1);
                    float l0 = v0 - __bfloat162float(h0), l1 = v1 - __bfloat162float(h1);
                    __nv_bfloat162 hh = __halves2bfloat162(h0, h1);
                    __nv_bfloat162 ll = __halves2bfloat162(__float2bfloat16_rn(l0), __float2bfloat16_rn(l1));
                    const size_t off = (size_t)(row + hrow * 8) * ldc + col;
                    *(uint32_t*)(Chi + off) = *(uint32_t*)&hh;
                    *(uint32_t*)(Clo + off) = *(uint32_t*)&ll;
                }
            }
        }
    }
}

// ================= fp16 single-term engine (gates path; R16 body) =================
#define STAGE_H 49152
#define SMEM_H  (2 * STAGE_H)

template <int KV>
__device__ void gemm_h1_body(
    const __half* __restrict__ A, const __half* __restrict__ B,
    int mBase, int nBaseB, int nColOut, float* __restrict__ C, int ldc)
{
    extern __shared__ char smem[];
    const uint32_t sbase = smem_u32(smem);
    const int tid  = threadIdx.x;
    const int wid  = tid >> 5, lane = tid & 31;
    const int wm   = wid & 3,  wn   = wid >> 2;

    float acc[4][8][4];
#pragma unroll
    for (int i = 0; i < 4; i++)
#pragma unroll
        for (int j = 0; j < 8; j++)
#pragma unroll
            for (int q = 0; q < 4; q++) acc[i][j][q] = 0.f;

    const int r0 = tid >> 3, c16v = tid & 7;
    const __half* pA = A + (size_t)(mBase + r0) * KV + c16v * 8;
    const __half* pB = B + (size_t)(nBaseB + r0) * KV + c16v * 8;
    const uint32_t swz0 = sw128((uint32_t)r0 * 128u + (uint32_t)c16v * 16u);

    auto issue = [&](uint32_t stg) {
        const uint32_t d0 = stg + swz0;
#pragma unroll
        for (int j = 0; j < 8; j++) cp16(d0 +          j * 4096u, pA + (size_t)j * 32 * KV);
#pragma unroll
        for (int j = 0; j < 4; j++) cp16(d0 + 32768u + j * 4096u, pB + (size_t)j * 32 * KV);
        asm volatile("cp.async.commit_group;" ::: "memory");
        pA += 64; pB += 64;
    };

    const int g = lane >> 3, r = lane & 7;
    const uint32_t a_row  = (uint32_t)(wm * 64 + (g & 1) * 8 + r);
    const uint32_t a_colb = (uint32_t)((g >> 1) * 16);
    const uint32_t b_row  = (uint32_t)(wn * 64 + (g >> 1) * 8 + r);
    const uint32_t b_colb = (uint32_t)((g & 1) * 16);

    constexpr int NC = KV >> 6;
    issue(sbase);

    for (int c = 0; c < NC; c++) {
        const int buf = c & 1;
        if (c + 1 < NC) {
            issue(sbase + (uint32_t)(buf ^ 1) * STAGE_H);
            asm volatile("cp.async.wait_group 1;" ::: "memory");
        } else {
            asm volatile("cp.async.wait_group 0;" ::: "memory");
        }
        __syncthreads();

        const uint32_t stage = sbase + (uint32_t)buf * STAGE_H;
        const uint32_t Ah = stage, Bh = stage + 32768u;
#pragma unroll
        for (int k16 = 0; k16 < 4; k16++) {
            uint32_t af[4][4];
#pragma unroll
            for (int i = 0; i < 4; i++) {
                uint32_t off = sw128((a_row + (uint32_t)i * 16u) * 128u
                                     + (uint32_t)k16 * 32u + a_colb);
                ldsm4(af[i], Ah + off);
            }
            uint32_t bf[2][4];
            {
                uint32_t off = sw128(b_row * 128u + (uint32_t)k16 * 32u + b_colb);
                ldsm4(bf[0], Bh + off);
            }
#pragma unroll
            for (int j2 = 0; j2 < 4; j2++) {
                const int cur = j2 & 1, nxt = cur ^ 1;
                if (j2 < 3) {
                    uint32_t off = sw128((b_row + (uint32_t)(j2 + 1) * 16u) * 128u
                                         + (uint32_t)k16 * 32u + b_colb);
                    ldsm4(bf[nxt], Bh + off);
                }
#pragma unroll
                for (int i = 0; i < 4; i++) {
                    mma_f16(acc[i][2 * j2],     af[i], bf[cur]);
                    mma_f16(acc[i][2 * j2 + 1], af[i], bf[cur] + 2);
                }
            }
        }
        __syncthreads();
    }

    const int rr = lane >> 2, cc = (lane & 3) * 2;
#pragma unroll
    for (int i = 0; i < 4; i++) {
        const int row = mBase + wm * 64 + i * 16 + rr;
#pragma unroll
        for (int j = 0; j < 8; j++) {
            const int col = nColOut + wn * 64 + j * 8 + cc;
            *(float2*)(C + (size_t)row * ldc + col)       = make_float2(acc[i][j][0], acc[i][j][1]);
            *(float2*)(C + (size_t)(row + 8) * ldc + col) = make_float2(acc[i][j][2], acc[i][j][3]);
        }
    }
}

// ---------------- GEMM wrapper kernels ----------------
__global__ void __launch_bounds__(NTHREADS, 1) k_pre_gemm()        // q/k/v/decay cols 0..3199 (pair)
{
    const int mBase = blockIdx.y * 256, nBase = blockIdx.x * 128;
    gemm_tc_body<0, 1024>(g_xhi, g_xlo, g_WThi, g_WTlo, mBase, nBase, mBase, nBase,
                          g_pre, nullptr, nullptr, NBIG);
}

__global__ void __launch_bounds__(NTHREADS, 1) k_pre_gemm_h()      // gate+ogate cols 3200..5247 (fp16)
{
    const int mBase = blockIdx.y * 256, nB = blockIdx.x * 128;     // nB in [0,2048)
    gemm_h1_body<1024>(g_x16, g_W16, mBase, nB, COL_GATE + nB, g_pre, NBIG);
}

__global__ void __launch_bounds__(NTHREADS, 1) k_weff_gemm()
{
    const int p = blockIdx.z;
    const int mBase = blockIdx.y * 256, nBase = blockIdx.x * 128;
    const size_t off = (size_t)p * 1024 * 1024;
    const int mOut = (p < 3 ? p * 1024 : 3200) + mBase;   // gate staged at rows 3200..4223
    gemm_tc_body<1, 1024>(g_VThi + off, g_VTlo + off, g_Uchi + off, g_Uclo + off,
                          mBase, nBase, mOut, nBase,
                          nullptr, g_WThi, g_WTlo, D_MODEL);
}

__global__ void __launch_bounds__(NTHREADS, 1) k_final_gemm(float* __restrict__ out)
{
    const int mBase = blockIdx.y * 256, nBase = blockIdx.x * 128;
    gemm_tc_body<0, 1024>(g_yhi, g_ylo, g_ophi, g_oplo, mBase, nBase, mBase, nBase,
                          out, nullptr, nullptr, D_MODEL);
}

// ---------------- prep kernels ----------------
__global__ void topk_setup(const float* __restrict__ ql, const float* __restrict__ kl,
                           const float* __restrict__ vl, const float* __restrict__ gl)
{
    if (threadIdx.x != 0) return;
    const float* Ls[4] = {ql, kl, vl, gl};
    for (int p = 0; p < 4; p++) {
        float l[16];
        float m = -1e30f;
        for (int i = 0; i < 16; i++) { l[i] = Ls[p][i]; m = fmaxf(m, l[i]); }
        bool used[16] = {false};
        float s = 0.f;
        for (int k = 0; k < TOPK; k++) {
            int best = -1; float bvv = -1e30f;
            for (int i = 0; i < 16; i++)
                if (!used[i] && l[i] > bvv) { bvv = l[i]; best = i; }
            used[best] = true;
            g_idx[p][k] = best;
            float e = expf(l[best] - m);
            g_vals[p][k] = e;
            s += e;
        }
        for (int k = 0; k < TOPK; k++) g_vals[p][k] /= s;
    }
}

__global__ void conv_pair4(const float* __restrict__ src,
                           __nv_bfloat16* __restrict__ hi, __nv_bfloat16* __restrict__ lo, int n4)
{
    int i = blockIdx.x * 256 + threadIdx.x;
    if (i >= n4) return;
    float4 v = ((const float4*)src)[i];
    __nv_bfloat16 h0 = __float2bfloat16_rn(v.x), h1 = __float2bfloat16_rn(v.y);
    __nv_bfloat16 h2 = __float2bfloat16_rn(v.z), h3 = __float2bfloat16_rn(v.w);
    __nv_bfloat162 hA = __halves2bfloat162(h0, h1), hB = __halves2bfloat162(h2, h3);
    __nv_bfloat162 lA = __halves2bfloat162(__float2bfloat16_rn(v.x - __bfloat162float(h0)),
                                           __float2bfloat16_rn(v.y - __bfloat162float(h1)));
    __nv_bfloat162 lB = __halves2bfloat162(__float2bfloat16_rn(v.z - __bfloat162float(h2)),
                                           __float2bfloat16_rn(v.w - __bfloat162float(h3)));
    ((uint2*)hi)[i] = make_uint2(*(uint32_t*)&hA, *(uint32_t*)&hB);
    ((uint2*)lo)[i] = make_uint2(*(uint32_t*)&lA, *(uint32_t*)&lB);
}

__global__ void conv_h4(const float* __restrict__ src, __half* __restrict__ dst, int n4)
{
    int i = blockIdx.x * 256 + threadIdx.x;
    if (i >= n4) return;
    float4 v = ((const float4*)src)[i];
    __half2 a = __floats2half2_rn(v.x, v.y);
    __half2 b = __floats2half2_rn(v.z, v.w);
    ((uint2*)dst)[i] = make_uint2(*(uint32_t*)&a, *(uint32_t*)&b);
}

// Uc(p)[d, ks*256+r] = U_p[prim(ks)][d, r]
__global__ void build_Uc(const float* __restrict__ qU, const float* __restrict__ kU,
                         const float* __restrict__ vU)
{
    const int p = blockIdx.y;
    const float* U = (p == 0) ? qU : (p == 1) ? kU : vU;
    int i = blockIdx.x * 256 + threadIdx.x;
    int d = i >> 10, kk = i & 1023, ks = kk >> 8, rr = kk & 255;
    int prim = g_idx[p][ks];
    float v = U[(size_t)prim * (D_MODEL * RANK) + (size_t)d * RANK + rr];
    __nv_bfloat16 h = __float2bfloat16_rn(v);
    size_t off = (size_t)p * 1048576 + i;
    g_Uchi[off] = h;
    g_Uclo[off] = __float2bfloat16_rn(v - __bfloat162float(h));
}

// VT(p)[o, ks*256+r] = vals[p][ks] * V_p[prim(ks)][r, o]
__global__ void build_VT(const float* __restrict__ qV, const float* __restrict__ kV,
                         const float* __restrict__ vV)
{
    __shared__ float tile[32][33];
    const int z = blockIdx.z;
    const int p = z >> 2, ks = z & 3;
    const float* V = (p == 0) ? qV : (p == 1) ? kV : vV;
    const int prim = g_idx[p][ks];
    const float w = g_vals[p][ks];
    const float* Vp = V + (size_t)prim * (RANK * HIDDEN);
    const int r0 = blockIdx.x * 32, o0 = blockIdx.y * 32;
#pragma unroll
    for (int j = 0; j < 32; j += 8)
        tile[threadIdx.y + j][threadIdx.x] = Vp[(size_t)(r0 + threadIdx.y + j) * HIDDEN + o0 + threadIdx.x];
    __syncthreads();
#pragma unroll
    for (int j = 0; j < 32; j += 8) {
        float v = w * tile[threadIdx.x][threadIdx.y + j];
        size_t off = (size_t)p * 1048576 + (size_t)(o0 + threadIdx.y + j) * 1024 + ks * 256 + r0 + threadIdx.x;
        __nv_bfloat16 h = __float2bfloat16_rn(v);
        g_VThi[off] = h;
        g_VTlo[off] = __float2bfloat16_rn(v - __bfloat162float(h));
    }
}

// pair rows 3072..3199: decay_w (16 rows) + zero pad (112 rows)
__global__ void pack_tail(const float* __restrict__ dw)
{
    int i = blockIdx.x * 256 + threadIdx.x;     // over 128*1024
    if (i >= 128 * 1024) return;
    int rr = i >> 10, d = i & 1023;
    float v = (rr < 16) ? dw[rr * D_MODEL + d] : 0.f;
    size_t off = (size_t)(3072 + rr) * D_MODEL + d;
    __nv_bfloat16 h = __float2bfloat16_rn(v);
    g_WThi[off] = h;
    g_WTlo[off] = __float2bfloat16_rn(v - __bfloat162float(h));
}

// gate rows: g_W16[0..1023] = fp16(WThi+WTlo rows 3200..4223)
__global__ void repack_gate(void)
{
    int i = blockIdx.x * 256 + threadIdx.x;      // over 1024*1024
    size_t src = (size_t)3200 * 1024 + i;
    float v = __bfloat162float(g_WThi[src]) + __bfloat162float(g_WTlo[src]);
    g_W16[i] = __float2half_rn(v);
}

// ogate rows: g_W16[1024..2047] = fp16(out_gate_w)
__global__ void pack_ogate(const float* __restrict__ ogw)
{
    int i = blockIdx.x * 256 + threadIdx.x;      // over 1024*1024
    g_W16[1048576 + i] = __float2half_rn(ogw[i]);
}

// ---------------- pointwise: kv = sigmoid(gate)*k*v ; log_decay = -softplus(z + b) ----------------
__global__ void pointwise(const float* __restrict__ decay_b)
{
    const int row = blockIdx.y;
    const int col = blockIdx.x * 256 + threadIdx.x;
    const size_t base = (size_t)row * NBIG;
    float kk = g_pre[base + 1024 + col];
    float vv = g_pre[base + 2048 + col];
    float gt = g_pre[base + COL_GATE + col];
    g_kv[(size_t)row * HIDDEN + col] = kk * vv / (1.f + expf(-gt));
    if (blockIdx.x == 0 && threadIdx.x < NHEADS) {
        float z = g_pre[base + COL_DECAY + threadIdx.x] + decay_b[threadIdx.x];
        float sp = fmaxf(z, 0.f) + log1pf(expf(-fabsf(z)));
        g_ld[row * NHEADS + threadIdx.x] = -sp;
    }
}

// ---------------- chunked scan ----------------
__global__ void scan_pass1()
{
    const int b = blockIdx.z, h = blockIdx.y, c = blockIdx.x, d = threadIdx.x;
    const int row0 = b * SEQ + c * CHUNKSZ;
    float s = 0.f, cum = 0.f;
    for (int t = 0; t < CHUNKSZ; t++) {
        const int row = row0 + t;
        float ld = g_ld[row * NHEADS + h];
        cum += ld;
        s = s * expf(ld) + g_kv[(size_t)row * HIDDEN + h * DHEAD + d];
    }
    const int ci = (b * NHEADS + h) * NCHUNK + c;
    g_Y[ci * DHEAD + d] = s;
    if (d == 0) g_Adec[ci] = expf(cum);
}

__global__ void scan_pass2()
{
    const int h = blockIdx.x, b = blockIdx.y, d = threadIdx.x;
    const int base = (b * NHEADS + h) * NCHUNK;
    float s = 0.f;
    for (int c = 0; c < NCHUNK; c++) {
        g_Sin[(base + c) * DHEAD + d] = s;
        s = g_Adec[base + c] * s + g_Y[(base + c) * DHEAD + d];
    }
}

__global__ void scan_pass3()
{
    const int b = blockIdx.z, h = blockIdx.y, c = blockIdx.x, d = threadIdx.x;
    const int ci = (b * NHEADS + h) * NCHUNK + c;
    const int row0 = b * SEQ + c * CHUNKSZ;
    float s = g_Sin[ci * DHEAD + d];
    for (int t = 0; t < CHUNKSZ; t++) {
        const int row = row0 + t;
        float ld = g_ld[row * NHEADS + h];
        s = s * expf(ld) + g_kv[(size_t)row * HIDDEN + h * DHEAD + d];
        float q = g_pre[(size_t)row * NBIG + h * DHEAD + d];
        g_out[(size_t)row * HIDDEN + h * DHEAD + d] = q * s;
    }
}

// ---------------- RMS-norm + output gate -> bf16 pair ----------------
__global__ void rms_gate(const float* __restrict__ rms_w)
{
    const int row = blockIdx.x;
    const int tid = threadIdx.x;
    const float* o = g_out + (size_t)row * HIDDEN;
    float ss = 0.f;
    for (int c = tid; c < HIDDEN; c += 256) { float x = o[c]; ss += x * x; }
#pragma unroll
    for (int w = 16; w; w >>= 1) ss += __shfl_xor_sync(0xffffffffu, ss, w);
    __shared__ float red[8];
    if ((tid & 31) == 0) red[tid >> 5] = ss;
    __syncthreads();
    __shared__ float s_rinv;
    if (tid < 8) {
        float v = red[tid];
#pragma unroll
        for (int w = 4; w; w >>= 1) v += __shfl_xor_sync(0xffu, v, w);
        if (tid == 0) s_rinv = rsqrtf(v * (1.f / 1024.f) + 1.1920929e-07f);
    }
    __syncthreads();
    const float rinv = s_rinv;
    for (int c = tid; c < HIDDEN; c += 256) {
        float g = g_pre[(size_t)row * NBIG + COL_OGATE + c];
        float y = o[c] * rinv * rms_w[c] / (1.f + expf(-g));
        __nv_bfloat16 h = __float2bfloat16_rn(y);
        size_t off = (size_t)row * HIDDEN + c;
        g_yhi[off] = h;
        g_ylo[off] = __float2bfloat16_rn(y - __bfloat162float(h));
    }
}

// ---------------- launch ----------------
extern "C" void kernel_launch(void* const* d_in, const int* in_sizes, int n_in,
                              void* d_out, int out_size)
{
    (void)in_sizes; (void)n_in; (void)out_size;
    const float* x    = (const float*)d_in[0];
    const float* qU   = (const float*)d_in[1];
    const float* qV   = (const float*)d_in[2];
    const float* kU   = (const float*)d_in[3];
    const float* kV   = (const float*)d_in[4];
    const float* vU   = (const float*)d_in[5];
    const float* vV   = (const float*)d_in[6];
    const float* ql   = (const float*)d_in[7];
    const float* kl   = (const float*)d_in[8];
    const float* vl   = (const float*)d_in[9];
    const float* gl   = (const float*)d_in[10];
    const float* dw   = (const float*)d_in[11];
    const float* db   = (const float*)d_in[12];
    const float* ogw  = (const float*)d_in[13];
    const float* opw  = (const float*)d_in[14];
    const float* rmsw = (const float*)d_in[15];
    float* out = (float*)d_out;

    void *p_xhi, *p_xlo, *p_x16, *p_ophi, *p_oplo;
    cudaGetSymbolAddress(&p_xhi,  g_xhi);
    cudaGetSymbolAddress(&p_xlo,  g_xlo);
    cudaGetSymbolAddress(&p_x16,  g_x16);
    cudaGetSymbolAddress(&p_ophi, g_ophi);
    cudaGetSymbolAddress(&p_oplo, g_oplo);

    cudaFuncSetAttribute(k_pre_gemm,   cudaFuncAttributeMaxDynamicSharedMemorySize, SMEM_GEMM);
    cudaFuncSetAttribute(k_pre_gemm_h, cudaFuncAttributeMaxDynamicSharedMemorySize, SMEM_H);
    cudaFuncSetAttribute(k_weff_gemm,  cudaFuncAttributeMaxDynamicSharedMemorySize, SMEM_GEMM);
    cudaFuncSetAttribute(k_final_gemm, cudaFuncAttributeMaxDynamicSharedMemorySize, SMEM_GEMM);

    // launch order keeps k_weff_gemm as launch #3 (profiled)
    topk_setup<<<1, 32>>>(ql, kl, vl, gl);                                   // 0
    build_Uc<<<dim3(4096, 4), 256>>>(qU, kU, vU);                            // 1
    build_VT<<<dim3(8, 32, 16), dim3(32, 8)>>>(qV, kV, vV);                  // 2
    k_weff_gemm<<<dim3(8, 4, 4), NTHREADS, SMEM_GEMM>>>();                   // 3 (profiled)
    conv_pair4<<<(NTOK * D_MODEL / 4 + 255) / 256, 256>>>(x, (__nv_bfloat16*)p_xhi, (__nv_bfloat16*)p_xlo, NTOK * D_MODEL / 4);
    conv_h4<<<(NTOK * D_MODEL / 4 + 255) / 256, 256>>>(x, (__half*)p_x16, NTOK * D_MODEL / 4);
    conv_pair4<<<(D_MODEL * HIDDEN / 4 + 255) / 256, 256>>>(opw, (__nv_bfloat16*)p_ophi, (__nv_bfloat16*)p_oplo, D_MODEL * HIDDEN / 4);
    pack_tail<<<(128 * 1024 + 255) / 256, 256>>>(dw);   // decay rows into pair weights
    repack_gate<<<4096, 256>>>();                       // gate W -> fp16 (after weff)
    pack_ogate<<<4096, 256>>>(ogw);                     // ogate W -> fp16
    // projection GEMMs: q/k/v/decay (bf16 pair, 25 tiles) + gate/ogate (fp16, 16 tiles)
    k_pre_gemm  <<<dim3(25, NTOK / 256), NTHREADS, SMEM_GEMM>>>();
    k_pre_gemm_h<<<dim3(16, NTOK / 256), NTHREADS, SMEM_H>>>();
    // pointwise kv + log_decay
    pointwise<<<dim3(4, NTOK), 256>>>(db);
    // chunked scan
    scan_pass1<<<dim3(NCHUNK, NHEADS, 4), DHEAD>>>();
    scan_pass2<<<dim3(NHEADS, 4), DHEAD>>>();
    scan_pass3<<<dim3(NCHUNK, NHEADS, 4), DHEAD>>>();
    // RMS norm + output gate (-> bf16 pair)
    rms_gate<<<NTOK, 256>>>(rmsw);
    // final projection
    k_final_gemm<<<dim3(D_MODEL / 128, NTOK / 256), NTHREADS, SMEM_GEMM>>>(out);
}